// round 17
// baseline (speedup 1.0000x reference)
#include <cuda_runtime.h>
#include <cuda_fp16.h>
#include <math.h>
#include <stdint.h>

// ---------------- problem constants ----------------
#define BB   2
#define LL   1024
#define DD   768
#define VV   32000
#define NLAYER 4
#define DIN  1536
#define NS   16
#define DCV  4
#define DTR  48
#define XDIM (DTR + 2*NS)  // 80
#define MROWS (BB*LL)      // 2048
#define XSPLIT 16
#define OSPLIT 3

// ktile counts (K/16) per operand buffer
#define KT_D   48          // K=768
#define KT_DIN 96          // K=1536
#define KT_DT  3           // K=48

#define GEMM_SMEM (3 * 8192 * 2 * 2)   // 3-stage ring, A+B, fp16 = 96KB

// ---------------- device scratch (no allocation allowed) ----------------
__device__ float    g_x    [MROWS*DD];
__device__ float    g_xz   [MROWS*2*DIN];
__device__ float4   g_duz  [MROWS*DIN];     // (delta, u, z, -) for scan
__device__ float    g_xdbl [MROWS*XDIM];
__device__ float    g_xpart[XSPLIT*MROWS*XDIM];
__device__ float    g_ypart[OSPLIT*MROWS*DD];

// A-operand buffers: fp16 in m16n8k16-fragment tile-image layout
__device__ __half   g_xn  [16*KT_D*2048];
__device__ __half   g_xbc [16*KT_DIN*2048];
__device__ __half   g_y   [16*KT_DIN*2048];
__device__ __half   g_dtA [16*KT_DT*2048];

// W-operand buffers: fp16 packed-B tile images (zero-padded)
__device__ __half   g_cw_in [NLAYER*24*KT_D*2048];
__device__ __half   g_cw_x  [NLAYER*1*KT_DIN*2048];
__device__ __half   g_cw_dt [NLAYER*12*KT_DT*2048];
__device__ __half   g_cw_out[NLAYER*6*KT_DIN*2048];
__device__ __half   g_cw_log[250*KT_D*2048];

// ---------------- helpers ----------------
__device__ __forceinline__ float softplusf(float x) {
    return fmaxf(x, 0.f) + log1pf(expf(-fabsf(x)));
}
__device__ __forceinline__ float siluf(float x) {
    return x / (1.f + expf(-x));
}
__device__ __forceinline__ void cp16(uint32_t dst, const void* src) {
    asm volatile("cp.async.cg.shared.global [%0], [%1], 16;\n"
                 :: "r"(dst), "l"(src));
}
#define CP_COMMIT() asm volatile("cp.async.commit_group;\n" ::: "memory")
#define CP_WAIT(n)  asm volatile("cp.async.wait_group %0;\n" :: "n"(n) : "memory")

// A-fragment half-index: element (row, col) of an M x (KT*16) fp16 operand.
__device__ __forceinline__ size_t a_swz(int row, int col, int KT) {
    int mtile = row >> 7, rm = row & 127;
    int bm = rm >> 4, r = rm & 15, fr = r & 7, rh = r >> 3;
    int kt = col >> 4, kl = col & 15;
    int q = (kl >> 1) & 3, kh = kl >> 3, lo = kl & 1;
    return ((((size_t)mtile * KT + kt) * 8 + bm) * 32 + (fr * 4 + q)) * 8
           + (kh * 2 + rh) * 2 + lo;
}

// ---------------- weight preconversion -> fp16 packed-B tile images -------
__global__ void __launch_bounds__(256)
wconvert_kernel(const float* __restrict__ w_in,
                const float* __restrict__ w_x,
                const float* __restrict__ w_dt,
                const float* __restrict__ w_out,
                const float* __restrict__ w_log) {
    __shared__ float sm[128][17];

    const int T_in  = NLAYER * 24 * KT_D;
    const int T_x   = NLAYER * 1  * KT_DIN;
    const int T_dt  = NLAYER * 12 * KT_DT;
    const int T_out = NLAYER * 6  * KT_DIN;

    int j = blockIdx.x;
    const float* src; __half* dst; int KT, Nreal, K, tile;
    if (j < T_in) {
        int l = j / (24 * KT_D); tile = j % (24 * KT_D);
        src = w_in + (size_t)l * 2 * DIN * DD;
        dst = g_cw_in + (size_t)l * 24 * KT_D * 2048;
        KT = KT_D; Nreal = 2 * DIN; K = DD;
    } else if ((j -= T_in) < T_x) {
        int l = j / KT_DIN; tile = j % KT_DIN;
        src = w_x + (size_t)l * XDIM * DIN;
        dst = g_cw_x + (size_t)l * KT_DIN * 2048;
        KT = KT_DIN; Nreal = XDIM; K = DIN;
    } else if ((j -= T_x) < T_dt) {
        int l = j / (12 * KT_DT); tile = j % (12 * KT_DT);
        src = w_dt + (size_t)l * DIN * DTR;
        dst = g_cw_dt + (size_t)l * 12 * KT_DT * 2048;
        KT = KT_DT; Nreal = DIN; K = DTR;
    } else if ((j -= T_dt) < T_out) {
        int l = j / (6 * KT_DIN); tile = j % (6 * KT_DIN);
        src = w_out + (size_t)l * DD * DIN;
        dst = g_cw_out + (size_t)l * 6 * KT_DIN * 2048;
        KT = KT_DIN; Nreal = DD; K = DIN;
    } else {
        j -= T_out; tile = j;
        src = w_log; dst = g_cw_log;
        KT = KT_D; Nreal = VV; K = DD;
    }
    int ntile = tile / KT, ktile = tile % KT;
    int col0 = ntile * 128, k0 = ktile * 16;

    int t = threadIdx.x;
    int c = t >> 1;
    int k8 = (t & 1) * 8;
    if (col0 + c < Nreal) {
        const float* p = src + (size_t)(col0 + c) * K + k0 + k8;
        float4 v0 = *(const float4*)p;
        float4 v1 = *(const float4*)(p + 4);
        sm[c][k8 + 0] = v0.x; sm[c][k8 + 1] = v0.y;
        sm[c][k8 + 2] = v0.z; sm[c][k8 + 3] = v0.w;
        sm[c][k8 + 4] = v1.x; sm[c][k8 + 5] = v1.y;
        sm[c][k8 + 6] = v1.z; sm[c][k8 + 7] = v1.w;
    } else {
        #pragma unroll
        for (int i = 0; i < 8; i++) sm[c][k8 + i] = 0.f;
    }
    __syncthreads();

    int p = t >> 5, lane = t & 31;
    int fr = lane >> 2, q = lane & 3;
    int ca = p * 16 + fr;
    int cb = ca + 8;
    int ka = 2 * q, kb = 2 * q + 8;
    __half2 h0 = __floats2half2_rn(sm[ca][ka], sm[ca][ka + 1]);
    __half2 h1 = __floats2half2_rn(sm[ca][kb], sm[ca][kb + 1]);
    __half2 h2 = __floats2half2_rn(sm[cb][ka], sm[cb][ka + 1]);
    __half2 h3 = __floats2half2_rn(sm[cb][kb], sm[cb][kb + 1]);
    uint4 o;
    o.x = *(uint32_t*)&h0; o.y = *(uint32_t*)&h1;
    o.z = *(uint32_t*)&h2; o.w = *(uint32_t*)&h3;
    ((uint4*)dst)[(size_t)tile * 256 + t] = o;
}
#define WCONV_BLOCKS (NLAYER*24*KT_D + NLAYER*KT_DIN + NLAYER*12*KT_DT \
                      + NLAYER*6*KT_DIN + 250*KT_D)

// ---------------- embedding gather ----------------
__global__ void embed_kernel(const int* __restrict__ tok,
                             const float* __restrict__ emb) {
    int idx = blockIdx.x * blockDim.x + threadIdx.x;
    if (idx >= MROWS * DD) return;
    int row = idx / DD, d = idx - row * DD;
    g_x[idx] = emb[tok[row] * DD + d];
}

// ---------------- rmsnorm (+ fused yreduce); out swizzled fp16 ------------
__global__ void rmsnorm_kernel(const float* __restrict__ w,
                               const float* __restrict__ yp) {
    int row = blockIdx.x;
    float* xr = g_x + row * DD;
    float vloc[3];
    float s = 0.f;
    #pragma unroll
    for (int j = 0; j < 3; j++) {
        int i = threadIdx.x + j * 256;
        float v = xr[i];
        if (yp) {
            v += yp[(size_t)row * DD + i]
               + yp[(size_t)(MROWS + row) * DD + i]
               + yp[(size_t)(2 * MROWS + row) * DD + i];
            xr[i] = v;
        }
        vloc[j] = v;
        s += v * v;
    }
    __shared__ float red[8];
    #pragma unroll
    for (int o = 16; o; o >>= 1) s += __shfl_xor_sync(~0u, s, o);
    if ((threadIdx.x & 31) == 0) red[threadIdx.x >> 5] = s;
    __syncthreads();
    if (threadIdx.x < 8) {
        float v = red[threadIdx.x];
        #pragma unroll
        for (int o = 4; o; o >>= 1) v += __shfl_xor_sync(0xff, v, o);
        if (threadIdx.x == 0) red[0] = v;
    }
    __syncthreads();
    float rstd = rsqrtf(red[0] / (float)DD + 1e-5f);
    #pragma unroll
    for (int j = 0; j < 3; j++) {
        int i = threadIdx.x + j * 256;
        g_xn[a_swz(row, i, KT_D)] = __float2half_rn(vloc[j] * rstd * w[i]);
    }
}

// ---------------- causal depthwise conv (DC=4) + silu ----------------
// writes u (fp16, x_proj A) and packs (0, u, z) into g_duz for the scan.
__global__ void conv_silu_kernel(const float* __restrict__ w,
                                 const float* __restrict__ bias) {
    int idx = blockIdx.x * blockDim.x + threadIdx.x;
    if (idx >= MROWS * DIN) return;
    int c = idx % DIN;
    int row = idx / DIN;
    int t = row % LL;
    float acc = bias[c];
    #pragma unroll
    for (int j = 0; j < DCV; j++) {
        int tt = t - (DCV - 1) + j;
        if (tt >= 0)
            acc += w[c * DCV + j] * g_xz[(row - (DCV - 1) + j) * (2 * DIN) + c];
    }
    float s = siluf(acc);
    float z = g_xz[(size_t)row * (2 * DIN) + DIN + c];
    g_xbc[a_swz(row, c, KT_DIN)] = __float2half_rn(s);
    g_duz[idx] = make_float4(0.f, s, z, 0.f);
}

// ---------------- FP16 GEMM v10: 3-stage cp.async ring --------------------
// C[M,N] = A[M,K] @ W[N,K]^T (+bias)(+softplus). CTA tile 128x128, 8 warps
// (warp 64x32 via 4x4 m16n8k16). Stage = up to 4 k16 tile-images; 3-stage
// ring (prefetch depth 2), CP_WAIT(1) overlap. m-fastest grid. Split-K via
// blockIdx.z*ktchunk. Dynamic smem = GEMM_SMEM.
__global__ void __launch_bounds__(256, 2)
tgemm_kernel(const __half* __restrict__ A, const __half* __restrict__ W,
             const float* __restrict__ bias, float* __restrict__ C,
             int M, int N, int KTA, int KTW, int ldc, int act,
             int ktchunk, int cstride) {
    extern __shared__ __align__(16) __half dsm[];
    __half* As = dsm;                  // [3][8192]
    __half* Bs = dsm + 3 * 8192;       // [3][8192]

    int tid = threadIdx.x;
    int lane = tid & 31, warp = tid >> 5;
    int wm16 = (warp & 1) * 4;
    int wnp0 = (warp >> 1) * 2;
    int kt_base = blockIdx.z * ktchunk;
    C += (size_t)blockIdx.z * M * ldc;

    const __half* Abase = A + ((size_t)blockIdx.x * KTA + kt_base) * 2048
                            + tid * 8;
    const __half* Bbase = W + ((size_t)blockIdx.y * KTW + kt_base) * 2048
                            + tid * 8;

    uint32_t sA[3], sB[3];
    #pragma unroll
    for (int b = 0; b < 3; b++) {
        sA[b] = (uint32_t)__cvta_generic_to_shared(&As[b * 8192 + tid * 8]);
        sB[b] = (uint32_t)__cvta_generic_to_shared(&Bs[b * 8192 + tid * 8]);
    }

    float acc[4][4][4];
    #pragma unroll
    for (int i = 0; i < 4; i++)
        #pragma unroll
        for (int j = 0; j < 4; j++)
            #pragma unroll
            for (int r = 0; r < 4; r++) acc[i][j][r] = 0.f;

    int nst = (ktchunk + 3) >> 2;

    #define STAGE(s_, buf_)                                                  \
    {                                                                        \
        int base_ = 4 * (s_);                                                \
        int nin_ = ktchunk - base_; if (nin_ > 4) nin_ = 4;                  \
        const __half* a_ = Abase + (size_t)base_ * 2048;                     \
        const __half* b_ = Bbase + (size_t)base_ * 2048;                     \
        for (int i_ = 0; i_ < nin_; i_++) {                                  \
            cp16(sA[buf_] + i_ * 4096, a_ + i_ * 2048);                      \
            cp16(sB[buf_] + i_ * 4096, b_ + i_ * 2048);                      \
        }                                                                    \
        CP_COMMIT();                                                         \
    }

    #define CONSUME(buf_, t_)                                                \
    {                                                                        \
        int toff_ = (buf_) * 8192 + (t_) * 2048;                             \
        uint4 af[4], bq[2];                                                  \
        _Pragma("unroll")                                                    \
        for (int mt = 0; mt < 4; mt++)                                       \
            af[mt] = *(const uint4*)                                         \
                &As[toff_ + (wm16 + mt) * 256 + lane * 8];                   \
        _Pragma("unroll")                                                    \
        for (int np = 0; np < 2; np++)                                       \
            bq[np] = *(const uint4*)                                         \
                &Bs[toff_ + (wnp0 + np) * 256 + lane * 8];                   \
        uint32_t bf[4][2] = {                                                \
            {bq[0].x, bq[0].y}, {bq[0].z, bq[0].w},                          \
            {bq[1].x, bq[1].y}, {bq[1].z, bq[1].w}};                         \
        _Pragma("unroll")                                                    \
        for (int mt = 0; mt < 4; mt++)                                       \
            _Pragma("unroll")                                                \
            for (int nt = 0; nt < 4; nt++) {                                 \
                asm volatile(                                                \
                    "mma.sync.aligned.m16n8k16.row.col.f32.f16.f16.f32 "     \
                    "{%0,%1,%2,%3}, {%4,%5,%6,%7}, {%8,%9}, {%0,%1,%2,%3};"  \
                    : "+f"(acc[mt][nt][0]), "+f"(acc[mt][nt][1]),            \
                      "+f"(acc[mt][nt][2]), "+f"(acc[mt][nt][3])             \
                    : "r"(af[mt].x), "r"(af[mt].y),                          \
                      "r"(af[mt].z), "r"(af[mt].w),                          \
                      "r"(bf[nt][0]), "r"(bf[nt][1]));                       \
            }                                                                \
    }

    STAGE(0, 0);
    if (nst > 1) STAGE(1, 1);
    int buf = 0, nbuf = 2;
    for (int s = 0; s < nst; s++) {
        if (s + 1 < nst) { CP_WAIT(1); } else { CP_WAIT(0); }
        __syncthreads();
        if (s + 2 < nst) STAGE(s + 2, nbuf);

        int nin = ktchunk - 4 * s; if (nin > 4) nin = 4;
        if (nin == 4) {
            #pragma unroll
            for (int t = 0; t < 4; t++) CONSUME(buf, t);
        } else {
            for (int t = 0; t < nin; t++) CONSUME(buf, t);
        }
        buf = (buf == 2) ? 0 : buf + 1;
        nbuf = (nbuf == 2) ? 0 : nbuf + 1;
    }
    #undef STAGE
    #undef CONSUME

    int m0 = blockIdx.x * 128, n0 = blockIdx.y * 128;
    int fr = lane >> 2;
    int fc = (lane & 3) * 2;
    #pragma unroll
    for (int mt = 0; mt < 4; mt++) {
        int row0 = m0 + (warp & 1) * 64 + mt * 16 + fr;
        #pragma unroll
        for (int nt = 0; nt < 4; nt++) {
            int n = n0 + (warp >> 1) * 32 + nt * 8 + fc;
            if (n < N) {
                if (cstride == 1) {
                    float2 v0 = make_float2(acc[mt][nt][0], acc[mt][nt][1]);
                    float2 v1 = make_float2(acc[mt][nt][2], acc[mt][nt][3]);
                    if (bias) {
                        float2 bv = *(const float2*)(bias + n);
                        v0.x += bv.x; v0.y += bv.y;
                        v1.x += bv.x; v1.y += bv.y;
                    }
                    if (act == 1) {
                        v0.x = softplusf(v0.x); v0.y = softplusf(v0.y);
                        v1.x = softplusf(v1.x); v1.y = softplusf(v1.y);
                    }
                    *(float2*)(C + (size_t)row0 * ldc + n) = v0;
                    *(float2*)(C + (size_t)(row0 + 8) * ldc + n) = v1;
                } else {
                    #pragma unroll
                    for (int r = 0; r < 4; r++) {
                        int m = row0 + (r >> 1) * 8;
                        int nn = n + (r & 1);
                        float v = acc[mt][nt][r];
                        if (bias)  v += bias[nn];
                        if (act == 1) v = softplusf(v);
                        C[((size_t)m * ldc + nn) * cstride] = v;
                    }
                }
            }
        }
    }
}

// ---------------- split-K reductions ----------------
__global__ void xreduce_kernel() {
    int idx = blockIdx.x * blockDim.x + threadIdx.x;
    if (idx >= MROWS * XDIM) return;
    float s = 0.f;
    #pragma unroll
    for (int z = 0; z < XSPLIT; z++)
        s += g_xpart[(size_t)z * MROWS * XDIM + idx];
    g_xdbl[idx] = s;
    int col = idx % XDIM;
    if (col < DTR) {
        int row = idx / XDIM;
        g_dtA[a_swz(row, col, KT_DT)] = __float2half_rn(s);
    }
}
// final residual fold + swizzled fp16 copy for logits A (fused xcvt)
__global__ void yreduce_kernel() {
    int idx = blockIdx.x * blockDim.x + threadIdx.x;
    if (idx >= MROWS * DD) return;
    float v = g_x[idx] + g_ypart[idx] + g_ypart[MROWS * DD + idx]
            + g_ypart[(size_t)2 * MROWS * DD + idx];
    int row = idx / DD, col = idx - row * DD;
    g_xn[a_swz(row, col, KT_D)] = __float2half_rn(v);
}

// ---------------- selective scan, 8-timestep batches ----------------
#define STB 8
__global__ void scan_kernel(const float* __restrict__ A_log,
                            const float* __restrict__ Dvec) {
    int half = threadIdx.x / 16;
    int ch = blockIdx.x * 16 + half;
    int lane = threadIdx.x & 15;
    int b = ch / DIN, d = ch % DIN;

    float An = -__expf(A_log[d * NS + lane]);
    float Dd = Dvec[d];

    const float4* duz = g_duz + (size_t)b * LL * DIN + d;
    const float* bcbase = g_xdbl + (size_t)b * LL * XDIM + DTR;

    float h = 0.f;
    for (int t0 = 0; t0 < LL; t0 += STB) {
        float4 du[STB]; float Bn[STB], Cn[STB];
        #pragma unroll
        for (int i = 0; i < STB; i++) {
            du[i] = duz[(size_t)(t0 + i) * DIN];
            Bn[i] = bcbase[(size_t)(t0 + i) * XDIM + lane];
            Cn[i] = bcbase[(size_t)(t0 + i) * XDIM + NS + lane];
        }

        float p[STB];
        #pragma unroll
        for (int i = 0; i < STB; i++) {
            float dA = __expf(du[i].x * An);
            h = fmaf(dA, h, du[i].x * Bn[i] * du[i].y);
            p[i] = h * Cn[i];
        }
        #pragma unroll
        for (int o = 8; o; o >>= 1) {
            #pragma unroll
            for (int i = 0; i < STB; i++)
                p[i] += __shfl_xor_sync(~0u, p[i], o);
        }
        if (lane == 0) {
            #pragma unroll
            for (int i = 0; i < STB; i++) {
                float yv = p[i] + du[i].y * Dd;
                float z = du[i].z;
                yv *= z / (1.f + __expf(-z));
                g_y[a_swz(b * LL + t0 + i, d, KT_DIN)] = __float2half_rn(yv);
            }
        }
    }
}

// ---------------- launch ----------------
extern "C" void kernel_launch(void* const* d_in, const int* in_sizes, int n_in,
                              void* d_out, int out_size) {
    const int*   tokens    = (const int*)  d_in[0];
    const float* emb       = (const float*)d_in[1];
    const float* Wout_w    = (const float*)d_in[2];
    const float* Wout_b    = (const float*)d_in[3];
    const float* norm_w    = (const float*)d_in[4];
    const float* in_proj_w = (const float*)d_in[5];
    const float* conv_w    = (const float*)d_in[6];
    const float* conv_b    = (const float*)d_in[7];
    const float* x_proj_w  = (const float*)d_in[8];
    const float* dt_proj_w = (const float*)d_in[9];
    const float* dt_proj_b = (const float*)d_in[10];
    const float* A_log     = (const float*)d_in[11];
    const float* Dvec      = (const float*)d_in[12];
    const float* out_projw = (const float*)d_in[13];
    float* out = (float*)d_out;

    static bool attr_set = false;
    if (!attr_set) {
        cudaFuncSetAttribute(tgemm_kernel,
                             cudaFuncAttributeMaxDynamicSharedMemorySize,
                             GEMM_SMEM);
        attr_set = true;
    }

    float *xz, *xpart, *ypart;
    float4* duz;
    __half *xn, *xbc, *y, *dtA, *cwin, *cwx, *cwdt, *cwout, *cwlog;
    cudaGetSymbolAddress((void**)&xz,    g_xz);
    cudaGetSymbolAddress((void**)&duz,   g_duz);
    cudaGetSymbolAddress((void**)&xpart, g_xpart);
    cudaGetSymbolAddress((void**)&ypart, g_ypart);
    cudaGetSymbolAddress((void**)&xn,    g_xn);
    cudaGetSymbolAddress((void**)&xbc,   g_xbc);
    cudaGetSymbolAddress((void**)&y,     g_y);
    cudaGetSymbolAddress((void**)&dtA,   g_dtA);
    cudaGetSymbolAddress((void**)&cwin,  g_cw_in);
    cudaGetSymbolAddress((void**)&cwx,   g_cw_x);
    cudaGetSymbolAddress((void**)&cwdt,  g_cw_dt);
    cudaGetSymbolAddress((void**)&cwout, g_cw_out);
    cudaGetSymbolAddress((void**)&cwlog, g_cw_log);

    wconvert_kernel<<<WCONV_BLOCKS, 256>>>(in_proj_w, x_proj_w, dt_proj_w,
                                           out_projw, Wout_w);
    embed_kernel<<<(MROWS * DD + 255) / 256, 256>>>(tokens, emb);

    for (int l = 0; l < NLAYER; l++) {
        rmsnorm_kernel<<<MROWS, 256>>>(norm_w + (size_t)l * DD,
                                       l == 0 ? nullptr : ypart);

        // in_proj: (2048 x 3072), K=768  (grid: m-fastest)
        {
            dim3 g(16, 24);
            tgemm_kernel<<<g, 256, GEMM_SMEM>>>(xn,
                cwin + (size_t)l * 24 * KT_D * 2048, nullptr, xz,
                MROWS, 2 * DIN, KT_D, KT_D, 2 * DIN, 0, KT_D, 1);
        }

        conv_silu_kernel<<<(MROWS * DIN + 255) / 256, 256>>>(
            conv_w + (size_t)l * DIN * DCV, conv_b + (size_t)l * DIN);

        // x_proj: (2048 x 80), K=1536, split-K=16 (256 CTAs)
        {
            dim3 g(16, 1, XSPLIT);
            tgemm_kernel<<<g, 256, GEMM_SMEM>>>(xbc,
                cwx + (size_t)l * KT_DIN * 2048, nullptr, xpart,
                MROWS, XDIM, KT_DIN, KT_DIN, XDIM, 0, KT_DIN / XSPLIT, 1);
            xreduce_kernel<<<(MROWS * XDIM + 255) / 256, 256>>>();
        }

        // dt_proj + bias + softplus -> g_duz[.].x (cstride=4): K=48
        {
            dim3 g(16, 12);
            tgemm_kernel<<<g, 256, GEMM_SMEM>>>(dtA,
                cwdt + (size_t)l * 12 * KT_DT * 2048,
                dt_proj_b + (size_t)l * DIN, (float*)duz,
                MROWS, DIN, KT_DT, KT_DT, DIN, 1, KT_DT, 4);
        }

        scan_kernel<<<(BB * DIN) / 16, 256>>>(A_log + (size_t)l * DIN * NS,
                                              Dvec + (size_t)l * DIN);

        // out_proj: (2048 x 768), K=1536, split-K=3
        {
            dim3 g(16, 6, OSPLIT);
            tgemm_kernel<<<g, 256, GEMM_SMEM>>>(y,
                cwout + (size_t)l * 6 * KT_DIN * 2048, nullptr, ypart,
                MROWS, DD, KT_DIN, KT_DIN, DD, 0, KT_DIN / OSPLIT, 1);
        }
    }

    // fold last out_proj partials + write swizzled logits A (fused xcvt)
    yreduce_kernel<<<(MROWS * DD + 255) / 256, 256>>>();

    // logits: (2048 x 32000), K=768, + bias  (grid: m-fastest, W L2 reuse)
    {
        dim3 g(16, 250);
        tgemm_kernel<<<g, 256, GEMM_SMEM>>>(xn, cwlog, Wout_b, out,
                                            MROWS, VV, KT_D, KT_D, VV,
                                            0, KT_D, 1);
    }
}